// round 1
// baseline (speedup 1.0000x reference)
#include <cuda_runtime.h>
#include <math.h>

// ---------------- problem constants (fixed shapes for this instance) --------
#define Bq    32
#define NTOK  3136
#define CIN   128
#define CP1   129
#define Hh    56
#define Wq    56
#define HW    3136          // 56*56
#define HO    28
#define WO    28
#define HWO   784           // 28*28
#define COUT  320
#define NG    196
#define NA    2940          // NTOK - NG
#define SEL   588           // ceil(3136*0.25) - 196
#define NOUT  784           // NG + SEL
#define SORTN 4096

// ---------------- scratch (device globals; no allocations allowed) ----------
__device__ float g_feat[Bq * CP1 * HW];      // scatter accumulators -> normalized feat+mask
__device__ float g_tmp [Bq * CP1 * HW];      // horizontal blur output
__device__ float g_fmap[Bq * HWO * COUT];    // conv output, NHWC layout
__device__ float g_pert[Bq * NA];            // perturbed confidences
__device__ int   g_idx [Bq * SEL];           // top-k indices (sorted order)

// ---------------- separable Gaussian (ksize=9, sigma=2), compile-time -------
// e^{-d^2/8} for d = 0..4 ; normalized by (sum)^1 per dimension (outer product
// equals the reference 2D normalized kernel up to fp noise).
__device__ __forceinline__ float gw9(int i) {
    const float e0 = 1.0f;
    const float e1 = 0.88249690258459546f;   // exp(-1/8)
    const float e2 = 0.60653065971263342f;   // exp(-4/8)
    const float e3 = 0.32465246735834974f;   // exp(-9/8)
    const float e4 = 0.13533528323661270f;   // exp(-16/8)
    const float S  = 1.0f + 2.0f*(e1 + e2 + e3 + e4); // 4.89803062578...
    int d = i - 4; d = d < 0 ? -d : d;
    float e = (d == 0) ? e0 : (d == 1) ? e1 : (d == 2) ? e2 : (d == 3) ? e3 : e4;
    return e / S;
}

// ---------------- kernel 0: zero the scatter buffer --------------------------
__global__ void k_zero() {
    int i = blockIdx.x * blockDim.x + threadIdx.x;
    float4* p = reinterpret_cast<float4*>(g_feat);
    const int n4 = (Bq * CP1 * HW) / 4;
    if (i < n4) p[i] = make_float4(0.f, 0.f, 0.f, 0.f);
}

// ---------------- kernel 1: token -> map scatter (atomics) -------------------
// block = 256 threads = 2 tokens x 128 channels
__global__ void k_scatter(const float* __restrict__ x, const float* __restrict__ pos) {
    int tok = blockIdx.x * 2 + (threadIdx.x >> 7);
    int c   = threadIdx.x & 127;
    if (tok >= Bq * NTOK) return;
    int b = tok / NTOK;

    float p0 = pos[(size_t)tok * 2 + 0];
    float p1 = pos[(size_t)tok * 2 + 1];
    p0 = fminf(fmaxf(p0, -1.f), 1.f);
    p1 = fminf(fmaxf(p1, -1.f), 1.f);
    // ((0.5*(loc+1.0))*W)-0.5 , round-half-even (matches jnp.round)
    int lx = (int)rintf(0.5f * (p0 + 1.0f) * (float)Wq - 0.5f);
    int ly = (int)rintf(0.5f * (p1 + 1.0f) * (float)Hh - 0.5f);
    lx = min(max(lx, 0), Wq - 1);
    ly = min(max(ly, 0), Hh - 1);
    int cell = ly * Wq + lx;

    atomicAdd(&g_feat[((size_t)b * CP1 + c) * HW + cell], x[(size_t)tok * CIN + c]);
    if (c == 0) atomicAdd(&g_feat[((size_t)b * CP1 + 128) * HW + cell], 1.0f);
}

// ---------------- kernel 2: normalize by count, binarize mask ---------------
__global__ void k_norm() {
    int cell = blockIdx.x * blockDim.x + threadIdx.x;
    if (cell >= Bq * HW) return;
    int b = cell / HW, cl = cell % HW;
    float* base = g_feat + (size_t)b * CP1 * HW + cl;
    float m = base[(size_t)128 * HW];
    float inv = (m > 0.f) ? (1.f / (m + 1e-6f)) : 0.f;   // feat/(m+eps) * (m>0)
    #pragma unroll 8
    for (int c = 0; c < 128; c++) base[(size_t)c * HW] *= inv;
    base[(size_t)128 * HW] = (m > 0.f) ? 1.f : 0.f;
}

// ---------------- kernel 3: horizontal 9-tap blur (129 channels) ------------
__global__ void k_blurh() {
    int idx = blockIdx.x * blockDim.x + threadIdx.x;
    if (idx >= Bq * CP1 * HW) return;
    int xx = idx % Wq;
    int rest = idx / Wq;
    int y = rest % Hh;
    int plane = rest / Hh;
    const float* row = g_feat + (size_t)plane * HW + y * Wq;
    float s = 0.f;
    #pragma unroll
    for (int i = 0; i < 9; i++) {
        int xi = xx + i - 4;
        if (xi >= 0 && xi < Wq) s += gw9(i) * row[xi];
    }
    g_tmp[idx] = s;
}

// ---------------- kernel 4: vertical blur + hole-fill combine ---------------
__global__ void k_blurv() {
    int cell = blockIdx.x * blockDim.x + threadIdx.x;
    if (cell >= Bq * HW) return;
    int b = cell / HW, cl = cell % HW;
    int y = cl / Wq, xx = cl % Wq;

    float* fb = g_feat + (size_t)b * CP1 * HW + cl;
    float mask = fb[(size_t)128 * HW];
    if (mask > 0.f) return;                       // (1-mask)==0 -> unchanged

    const float* tb = g_tmp + (size_t)b * CP1 * HW + xx;
    float wv[9]; int ro[9];
    #pragma unroll
    for (int i = 0; i < 9; i++) {
        int yy = y + i - 4;
        bool ok = (yy >= 0 && yy < Hh);
        wv[i] = ok ? gw9(i) : 0.f;
        ro[i] = ok ? yy * Wq : 0;
    }
    float fm = 0.f;
    #pragma unroll
    for (int i = 0; i < 9; i++) fm += wv[i] * tb[(size_t)128 * HW + ro[i]];
    float scale = (fm > 0.f) ? (1.f / fmaxf(fm, 1e-6f)) : 0.f;

    for (int c = 0; c < 128; c++) {
        float fi = 0.f;
        const float* tc = tb + (size_t)c * HW;
        #pragma unroll
        for (int i = 0; i < 9; i++) fi += wv[i] * tc[ro[i]];
        fb[(size_t)c * HW] = fb[(size_t)c * HW] + fi * scale;  // feat + (1-mask)*fi
    }
}

// ---------------- kernel 5: 3x3 stride-2 conv 128->320, write NHWC ----------
// Block: 224 threads. Tile: 8 out rows x 28 out cols x 16 out channels.
// Thread = (co_g in 0..3 -> 4 channels) x (px group -> 4 horizontal pixels).
__global__ void __launch_bounds__(224) k_conv(const float* __restrict__ w,
                                              const float* __restrict__ bias) {
    __shared__ float s_in[17 * 60];
    __shared__ __align__(16) float s_w[9 * 16];

    int b   = blockIdx.z;
    int oy0 = blockIdx.y * 8;
    int co0 = blockIdx.x * 16;
    int t   = threadIdx.x;
    int co_g = t & 3;
    int pg   = t >> 2;         // 0..55
    int gx   = pg % 7;         // horizontal group (4 px each)
    int gy   = pg / 7;         // 0..7

    float acc[4][4];
    #pragma unroll
    for (int o = 0; o < 4; o++)
        #pragma unroll
        for (int s = 0; s < 4; s++) acc[o][s] = 0.f;

    const float* inb = g_feat + (size_t)b * CP1 * HW;

    for (int ci = 0; ci < 128; ci++) {
        __syncthreads();
        // fill input tile: 17 rows x 57 cols (zero-padded), stride 60
        for (int i = t; i < 17 * 57; i += 224) {
            int r = i / 57, cc = i % 57;
            int iy = 2 * oy0 - 1 + r;
            int ix = cc - 1;
            float v = 0.f;
            if (iy >= 0 && iy < Hh && (unsigned)ix < (unsigned)Wq)
                v = inb[(size_t)ci * HW + iy * Wq + ix];
            s_in[r * 60 + cc] = v;
        }
        // fill weights: s_w[k][co_local], k = ky*3+kx
        if (t < 144) {
            int k = t >> 4, cl = t & 15;
            s_w[k * 16 + cl] = w[(((size_t)(co0 + cl)) * 128 + ci) * 9 + k];
        }
        __syncthreads();

        #pragma unroll
        for (int ky = 0; ky < 3; ky++) {
            float v[9];
            const float* rowp = &s_in[(2 * gy + ky) * 60 + 8 * gx];
            #pragma unroll
            for (int j = 0; j < 9; j++) v[j] = rowp[j];
            #pragma unroll
            for (int kx = 0; kx < 3; kx++) {
                float4 wv = *reinterpret_cast<const float4*>(&s_w[(ky * 3 + kx) * 16 + 4 * co_g]);
                #pragma unroll
                for (int sub = 0; sub < 4; sub++) {
                    float in = v[2 * sub + kx];
                    acc[0][sub] += in * wv.x;
                    acc[1][sub] += in * wv.y;
                    acc[2][sub] += in * wv.z;
                    acc[3][sub] += in * wv.w;
                }
            }
        }
    }

    int oy = oy0 + gy;
    if (oy < HO) {
        #pragma unroll
        for (int o = 0; o < 4; o++) {
            int co = co0 + 4 * co_g + o;
            float bs = bias[co];
            #pragma unroll
            for (int sub = 0; sub < 4; sub++) {
                int ox = 4 * gx + sub;
                g_fmap[((size_t)(b * HWO + oy * WO + ox)) * COUT + co] = acc[o][sub] + bs;
            }
        }
    }
}

// ---------------- bilinear helper (fmap is NHWC, 28x28x320) -----------------
struct Bilin { float w0, w1, w2, w3; const float *p0, *p1, *p2, *p3; };

__device__ __forceinline__ Bilin bilin_setup(int b, float px, float py) {
    float gx = ((px + 1.f) * (float)WO - 1.f) * 0.5f;
    float gy = ((py + 1.f) * (float)HO - 1.f) * 0.5f;
    float x0f = floorf(gx), y0f = floorf(gy);
    float wx = gx - x0f, wy = gy - y0f;
    int x0 = (int)x0f, y0 = (int)y0f;
    int x1 = x0 + 1,   y1 = y0 + 1;

    bool i00 = (x0 >= 0 && x0 < WO && y0 >= 0 && y0 < HO);
    bool i01 = (x1 >= 0 && x1 < WO && y0 >= 0 && y0 < HO);
    bool i10 = (x0 >= 0 && x0 < WO && y1 >= 0 && y1 < HO);
    bool i11 = (x1 >= 0 && x1 < WO && y1 >= 0 && y1 < HO);
    int x0c = min(max(x0, 0), WO - 1), x1c = min(max(x1, 0), WO - 1);
    int y0c = min(max(y0, 0), HO - 1), y1c = min(max(y1, 0), HO - 1);

    Bilin r;
    r.w0 = i00 ? (1.f - wx) * (1.f - wy) : 0.f;
    r.w1 = i01 ? wx * (1.f - wy)         : 0.f;
    r.w2 = i10 ? (1.f - wx) * wy         : 0.f;
    r.w3 = i11 ? wx * wy                 : 0.f;
    const float* base = g_fmap + (size_t)b * HWO * COUT;
    r.p0 = base + (size_t)(y0c * WO + x0c) * COUT;
    r.p1 = base + (size_t)(y0c * WO + x1c) * COUT;
    r.p2 = base + (size_t)(y1c * WO + x0c) * COUT;
    r.p3 = base + (size_t)(y1c * WO + x1c) * COUT;
    return r;
}

// ---------------- kernel 6: LN + confidence + gumbel (warp per ada token) ---
__global__ void k_conf(const float* __restrict__ pos,
                       const float* __restrict__ ln_g, const float* __restrict__ ln_b,
                       const float* __restrict__ cw, const float* __restrict__ cb,
                       const float* __restrict__ noise) {
    int wid  = (blockIdx.x * blockDim.x + threadIdx.x) >> 5;
    int lane = threadIdx.x & 31;
    if (wid >= Bq * NA) return;
    int b = wid / NA;
    int j = wid % NA;
    int n = NG + j;

    float p0 = pos[((size_t)b * NTOK + n) * 2 + 0];
    float p1 = pos[((size_t)b * NTOK + n) * 2 + 1];
    Bilin bl = bilin_setup(b, p0, p1);

    float s1 = 0.f, s2 = 0.f, sxw = 0.f, sgw = 0.f, sbw = 0.f;
    for (int c = lane; c < COUT; c += 32) {
        float xc = bl.w0 * bl.p0[c] + bl.w1 * bl.p1[c]
                 + bl.w2 * bl.p2[c] + bl.w3 * bl.p3[c];
        float wc = cw[c];
        float gv = ln_g[c] * wc;
        s1 += xc;
        s2 += xc * xc;
        sxw += xc * gv;
        sgw += gv;
        sbw += ln_b[c] * wc;
    }
    #pragma unroll
    for (int o = 16; o > 0; o >>= 1) {
        s1  += __shfl_xor_sync(0xffffffffu, s1,  o);
        s2  += __shfl_xor_sync(0xffffffffu, s2,  o);
        sxw += __shfl_xor_sync(0xffffffffu, sxw, o);
        sgw += __shfl_xor_sync(0xffffffffu, sgw, o);
        sbw += __shfl_xor_sync(0xffffffffu, sbw, o);
    }
    if (lane == 0) {
        float mu  = s1 * (1.f / (float)COUT);
        float var = s2 * (1.f / (float)COUT) - mu * mu;
        float rs  = rsqrtf(var + 1e-5f);
        float conf = rs * (sxw - mu * sgw) + sbw + cb[0];
        float nz = noise[(size_t)b * NA + j];
        float g  = -logf(-logf(nz + 1e-6f) + 1e-6f);
        g_pert[wid] = conf + g;   // T = 1.0
    }
}

// ---------------- kernel 7: per-batch top-k via bitonic sort -----------------
// Keys: descending value, ascending index on ties (matches jax.lax.top_k).
__global__ void __launch_bounds__(1024) k_sort() {
    __shared__ unsigned long long s[SORTN];
    int b = blockIdx.x;
    int t = threadIdx.x;

    for (int i = t; i < SORTN; i += 1024) {
        unsigned long long key;
        if (i < NA) {
            float v = g_pert[b * NA + i];
            unsigned u = __float_as_uint(v);
            u = (u & 0x80000000u) ? ~u : (u | 0x80000000u);   // monotone map
            key = (((unsigned long long)(~u)) << 32) | (unsigned)i; // flip: ascending sort => descending v
        } else {
            key = 0xFFFFFFFFFFFFFFFFull;
        }
        s[i] = key;
    }
    __syncthreads();

    for (int k = 2; k <= SORTN; k <<= 1) {
        for (int jj = k >> 1; jj > 0; jj >>= 1) {
            for (int i = t; i < SORTN; i += 1024) {
                int l = i ^ jj;
                if (l > i) {
                    unsigned long long a = s[i], c = s[l];
                    bool up = ((i & k) == 0);
                    if ((a > c) == up) { s[i] = c; s[l] = a; }
                }
            }
            __syncthreads();
        }
    }
    for (int i = t; i < SEL; i += 1024)
        g_idx[b * SEL + i] = (int)(unsigned)(s[i] & 0xFFFFFFFFull);
}

// ---------------- kernel 8: gather output (x_down then pos_down) -------------
__global__ void __launch_bounds__(320) k_gather(const float* __restrict__ pos,
                                                float* __restrict__ out) {
    int tok = blockIdx.x;              // 0 .. B*NOUT-1
    int b = tok / NOUT, j = tok % NOUT;
    int n = (j < NG) ? j : (NG + g_idx[b * SEL + (j - NG)]);

    float p0 = pos[((size_t)b * NTOK + n) * 2 + 0];
    float p1 = pos[((size_t)b * NTOK + n) * 2 + 1];
    Bilin bl = bilin_setup(b, p0, p1);

    int c = threadIdx.x;               // exactly 320 threads
    float xc = bl.w0 * bl.p0[c] + bl.w1 * bl.p1[c]
             + bl.w2 * bl.p2[c] + bl.w3 * bl.p3[c];
    out[(size_t)tok * COUT + c] = xc;

    if (c < 2) {
        float* po = out + (size_t)Bq * NOUT * COUT + (size_t)tok * 2;
        po[c] = (c == 0) ? p0 : p1;
    }
}

// ---------------- launcher ---------------------------------------------------
extern "C" void kernel_launch(void* const* d_in, const int* in_sizes, int n_in,
                              void* d_out, int out_size) {
    const float* x      = (const float*)d_in[0];
    const float* pos    = (const float*)d_in[1];
    const float* conv_w = (const float*)d_in[2];
    const float* conv_b = (const float*)d_in[3];
    const float* ln_g   = (const float*)d_in[4];
    const float* ln_b   = (const float*)d_in[5];
    const float* conf_w = (const float*)d_in[6];
    const float* conf_b = (const float*)d_in[7];
    const float* noise  = (const float*)d_in[8];
    float* out = (float*)d_out;

    {   // zero scatter buffer
        const int n4 = (Bq * CP1 * HW) / 4;
        k_zero<<<(n4 + 255) / 256, 256>>>();
    }
    k_scatter<<<(Bq * NTOK + 1) / 2, 256>>>(x, pos);
    k_norm<<<(Bq * HW + 255) / 256, 256>>>();
    k_blurh<<<(Bq * CP1 * HW + 255) / 256, 256>>>();
    k_blurv<<<(Bq * HW + 255) / 256, 256>>>();

    dim3 cgrid(COUT / 16, 4, Bq);      // 20 co-blocks, 4 row-tiles, 32 batches
    k_conv<<<cgrid, 224>>>(conv_w, conv_b);

    k_conf<<<(Bq * NA * 32) / 256, 256>>>(pos, ln_g, ln_b, conf_w, conf_b, noise);
    k_sort<<<Bq, 1024>>>();
    k_gather<<<Bq * NOUT, 320>>>(pos, out);
}

// round 2
// speedup vs baseline: 1.5046x; 1.5046x over previous
#include <cuda_runtime.h>
#include <math.h>

// ---------------- problem constants (fixed shapes for this instance) --------
#define Bq    32
#define NTOK  3136
#define CIN   128
#define CP1   129
#define Hh    56
#define Wq    56
#define HW    3136          // 56*56
#define HO    28
#define WO    28
#define HWO   784           // 28*28
#define COUT  320
#define NG    196
#define NA    2940          // NTOK - NG
#define SEL   588           // ceil(3136*0.25) - 196
#define NOUT  784           // NG + SEL
#define SORTN 4096
#define KTOT  1152          // 128*9

// ---------------- scratch (device globals; no allocations allowed) ----------
__device__ float g_feat[Bq * CP1 * HW];      // scatter accumulators -> normalized feat+mask
__device__ float g_tmp [Bq * CP1 * HW];      // horizontal blur output
__device__ float g_fmap[Bq * HWO * COUT];    // conv output, NHWC layout
__device__ float g_wT  [KTOT * COUT];        // transposed conv weights [ci*9+k][co]
__device__ float g_pert[Bq * NA];            // perturbed confidences
__device__ int   g_idx [Bq * SEL];           // top-k indices (sorted order)

// ---------------- separable Gaussian (ksize=9, sigma=2), compile-time -------
__device__ __forceinline__ float gw9(int i) {
    const float e0 = 1.0f;
    const float e1 = 0.88249690258459546f;   // exp(-1/8)
    const float e2 = 0.60653065971263342f;   // exp(-4/8)
    const float e3 = 0.32465246735834974f;   // exp(-9/8)
    const float e4 = 0.13533528323661270f;   // exp(-16/8)
    const float S  = 1.0f + 2.0f*(e1 + e2 + e3 + e4);
    int d = i - 4; d = d < 0 ? -d : d;
    float e = (d == 0) ? e0 : (d == 1) ? e1 : (d == 2) ? e2 : (d == 3) ? e3 : e4;
    return e / S;
}

// ---------------- packed f32x2 helpers (SASS FFMA2) --------------------------
__device__ __forceinline__ unsigned long long pack2(float x) {
    unsigned long long r;
    asm("mov.b64 %0, {%1, %1};" : "=l"(r) : "f"(x));
    return r;
}
__device__ __forceinline__ void fma2(unsigned long long& d,
                                     unsigned long long a, unsigned long long b) {
    asm("fma.rn.f32x2 %0, %1, %2, %0;" : "+l"(d) : "l"(a), "l"(b));
}
__device__ __forceinline__ float2 unpack2(unsigned long long v) {
    float2 f;
    asm("mov.b64 {%0, %1}, %2;" : "=f"(f.x), "=f"(f.y) : "l"(v));
    return f;
}

// ---------------- kernel 0: zero the scatter buffer --------------------------
__global__ void k_zero() {
    int i = blockIdx.x * blockDim.x + threadIdx.x;
    float4* p = reinterpret_cast<float4*>(g_feat);
    const int n4 = (Bq * CP1 * HW) / 4;
    if (i < n4) p[i] = make_float4(0.f, 0.f, 0.f, 0.f);
}

// ---------------- kernel 0b: transpose conv weights to [ci*9+k][co] ---------
__global__ void k_wtr(const float* __restrict__ w) {
    int i = blockIdx.x * blockDim.x + threadIdx.x;     // over COUT*KTOT
    if (i >= COUT * KTOT) return;
    int co = i / KTOT;
    int r  = i % KTOT;                                  // r = ci*9 + ky*3 + kx
    g_wT[(size_t)r * COUT + co] = w[i];
}

// ---------------- kernel 1: token -> map scatter (atomics) -------------------
__global__ void k_scatter(const float* __restrict__ x, const float* __restrict__ pos) {
    int tok = blockIdx.x * 2 + (threadIdx.x >> 7);
    int c   = threadIdx.x & 127;
    if (tok >= Bq * NTOK) return;
    int b = tok / NTOK;

    float p0 = pos[(size_t)tok * 2 + 0];
    float p1 = pos[(size_t)tok * 2 + 1];
    p0 = fminf(fmaxf(p0, -1.f), 1.f);
    p1 = fminf(fmaxf(p1, -1.f), 1.f);
    int lx = (int)rintf(0.5f * (p0 + 1.0f) * (float)Wq - 0.5f);
    int ly = (int)rintf(0.5f * (p1 + 1.0f) * (float)Hh - 0.5f);
    lx = min(max(lx, 0), Wq - 1);
    ly = min(max(ly, 0), Hh - 1);
    int cell = ly * Wq + lx;

    atomicAdd(&g_feat[((size_t)b * CP1 + c) * HW + cell], x[(size_t)tok * CIN + c]);
    if (c == 0) atomicAdd(&g_feat[((size_t)b * CP1 + 128) * HW + cell], 1.0f);
}

// ---------------- kernel 2: normalize by count, binarize mask ---------------
__global__ void k_norm() {
    int cell = blockIdx.x * blockDim.x + threadIdx.x;
    if (cell >= Bq * HW) return;
    int b = cell / HW, cl = cell % HW;
    float* base = g_feat + (size_t)b * CP1 * HW + cl;
    float m = base[(size_t)128 * HW];
    float inv = (m > 0.f) ? (1.f / (m + 1e-6f)) : 0.f;
    #pragma unroll 8
    for (int c = 0; c < 128; c++) base[(size_t)c * HW] *= inv;
    base[(size_t)128 * HW] = (m > 0.f) ? 1.f : 0.f;
}

// ---------------- kernel 3: horizontal 9-tap blur (smem rows, no branches) --
__global__ void __launch_bounds__(256) k_blurh() {
    __shared__ float s[4][64];
    int g   = blockIdx.x * 4 + (threadIdx.x >> 6);   // row id over Bq*CP1*Hh
    int sub = threadIdx.x >> 6;
    int lane = threadIdx.x & 63;

    float v = 0.f;
    int xx = lane - 4;                                // covers x -4..59
    if ((unsigned)xx < (unsigned)Wq)
        v = g_feat[(size_t)g * Wq + xx];
    s[sub][lane] = v;
    __syncthreads();

    if (lane < Wq) {
        float acc = 0.f;
        #pragma unroll
        for (int i = 0; i < 9; i++) acc += gw9(i) * s[sub][lane + i];
        g_tmp[(size_t)g * Wq + lane] = acc;
    }
}

// ---------------- kernel 4: vertical blur + hole-fill combine ---------------
__global__ void k_blurv() {
    int cell = blockIdx.x * blockDim.x + threadIdx.x;
    if (cell >= Bq * HW) return;
    int b = cell / HW, cl = cell % HW;
    int y = cl / Wq, xx = cl % Wq;

    float* fb = g_feat + (size_t)b * CP1 * HW + cl;
    float mask = fb[(size_t)128 * HW];
    if (mask > 0.f) return;

    const float* tb = g_tmp + (size_t)b * CP1 * HW + xx;
    float wv[9]; int ro[9];
    #pragma unroll
    for (int i = 0; i < 9; i++) {
        int yy = y + i - 4;
        bool ok = (yy >= 0 && yy < Hh);
        wv[i] = ok ? gw9(i) : 0.f;
        ro[i] = ok ? yy * Wq : 0;
    }
    float fm = 0.f;
    #pragma unroll
    for (int i = 0; i < 9; i++) fm += wv[i] * tb[(size_t)128 * HW + ro[i]];
    float scale = (fm > 0.f) ? (1.f / fmaxf(fm, 1e-6f)) : 0.f;

    for (int c = 0; c < 128; c++) {
        float fi = 0.f;
        const float* tc = tb + (size_t)c * HW;
        #pragma unroll
        for (int i = 0; i < 9; i++) fi += wv[i] * tc[ro[i]];
        fb[(size_t)c * HW] = fb[(size_t)c * HW] + fi * scale;
    }
}

// ---------------- kernel 5: 3x3 stride-2 conv 128->320 via packed FFMA2 -----
// Tile: 4 out rows x 28 out cols x 64 co. Block 224 threads.
// Thread: 4 co x 4 px x 2 rows (one row-pair) -> 16 f32x2 accumulators.
// Input row-pairs {iy, iy+2} pre-packed into float2 in smem; weights broadcast-
// packed {w,w} in registers; inner loop = 16 FFMA2 + 4 LDS.64 + 1 LDS.128/k.
#define CI_CHUNK 8
__global__ void __launch_bounds__(224) k_conv(const float* __restrict__ bias) {
    __shared__ float2 s_pack[CI_CHUNK][6][60];   // [ci][rp*3+ky][xx]  23,040 B
    __shared__ float  s_w  [CI_CHUNK][9][64];    // [ci][k][co_local]  18,432 B

    int b   = blockIdx.z;
    int oy0 = blockIdx.y * 4;
    int co0 = blockIdx.x * 64;
    int t   = threadIdx.x;
    int co_g = t & 15;          // 4 co each
    int px_g = (t >> 4) % 7;    // 4 px each
    int rp   = t / 112;         // 0..1 (row pair)

    unsigned long long acc[16]; // [o*4+sub] = {out_row y0, out_row y0+1}
    #pragma unroll
    for (int i = 0; i < 16; i++) acc[i] = 0ull;

    const float* inb = g_feat + (size_t)b * CP1 * HW;

    for (int cc = 0; cc < 128; cc += CI_CHUNK) {
        __syncthreads();
        // fill packed input tile: 8 ci x 6 pack-rows x 57 xx
        for (int i = t; i < CI_CHUNK * 6 * 57; i += 224) {
            int xx = i % 57;
            int pk = (i / 57) % 6;
            int ci = i / (57 * 6);
            int rp_f = pk / 3, ky = pk % 3;
            int iy_a = 2 * (oy0 + 2 * rp_f) - 1 + ky;
            int iy_b = iy_a + 2;
            int ix = xx - 1;
            const float* p = inb + (size_t)(cc + ci) * HW;
            float va = 0.f, vb = 0.f;
            if ((unsigned)ix < (unsigned)Wq) {
                if ((unsigned)iy_a < (unsigned)Hh) va = p[iy_a * Wq + ix];
                if ((unsigned)iy_b < (unsigned)Hh) vb = p[iy_b * Wq + ix];
            }
            s_pack[ci][pk][xx] = make_float2(va, vb);
        }
        // fill weights: 8 ci x 9 k x 64 co (coalesced from g_wT)
        for (int i = t; i < CI_CHUNK * 9 * 64; i += 224) {
            int co = i & 63;
            int k  = (i >> 6) % 9;
            int ci = i / (64 * 9);
            s_w[ci][k][co] = g_wT[((size_t)(cc + ci) * 9 + k) * COUT + co0 + co];
        }
        __syncthreads();

        for (int ci = 0; ci < CI_CHUNK; ci++) {
            #pragma unroll
            for (int ky = 0; ky < 3; ky++) {
                const float2* prow = &s_pack[ci][rp * 3 + ky][8 * px_g];
                #pragma unroll
                for (int kx = 0; kx < 3; kx++) {
                    const int k = ky * 3 + kx;
                    float4 w4 = *reinterpret_cast<const float4*>(&s_w[ci][k][co_g * 4]);
                    unsigned long long wp0 = pack2(w4.x);
                    unsigned long long wp1 = pack2(w4.y);
                    unsigned long long wp2 = pack2(w4.z);
                    unsigned long long wp3 = pack2(w4.w);
                    #pragma unroll
                    for (int sub = 0; sub < 4; sub++) {
                        unsigned long long a =
                            *reinterpret_cast<const unsigned long long*>(&prow[2 * sub + kx]);
                        fma2(acc[0 * 4 + sub], a, wp0);
                        fma2(acc[1 * 4 + sub], a, wp1);
                        fma2(acc[2 * 4 + sub], a, wp2);
                        fma2(acc[3 * 4 + sub], a, wp3);
                    }
                }
            }
        }
    }

    // epilogue: unpack, add bias, store NHWC
    int y0 = oy0 + 2 * rp;
    size_t base0 = ((size_t)b * HWO + y0 * WO) * COUT;
    #pragma unroll
    for (int o = 0; o < 4; o++) {
        int co = co0 + co_g * 4 + o;
        float bs = bias[co];
        #pragma unroll
        for (int sub = 0; sub < 4; sub++) {
            int px = px_g * 4 + sub;
            float2 f = unpack2(acc[o * 4 + sub]);
            g_fmap[base0 + (size_t)px * COUT + co]        = f.x + bs;
            g_fmap[base0 + (size_t)(WO + px) * COUT + co] = f.y + bs;
        }
    }
}

// ---------------- bilinear helper (fmap is NHWC, 28x28x320) -----------------
struct Bilin { float w0, w1, w2, w3; const float *p0, *p1, *p2, *p3; };

__device__ __forceinline__ Bilin bilin_setup(int b, float px, float py) {
    float gx = ((px + 1.f) * (float)WO - 1.f) * 0.5f;
    float gy = ((py + 1.f) * (float)HO - 1.f) * 0.5f;
    float x0f = floorf(gx), y0f = floorf(gy);
    float wx = gx - x0f, wy = gy - y0f;
    int x0 = (int)x0f, y0 = (int)y0f;
    int x1 = x0 + 1,   y1 = y0 + 1;

    bool i00 = (x0 >= 0 && x0 < WO && y0 >= 0 && y0 < HO);
    bool i01 = (x1 >= 0 && x1 < WO && y0 >= 0 && y0 < HO);
    bool i10 = (x0 >= 0 && x0 < WO && y1 >= 0 && y1 < HO);
    bool i11 = (x1 >= 0 && x1 < WO && y1 >= 0 && y1 < HO);
    int x0c = min(max(x0, 0), WO - 1), x1c = min(max(x1, 0), WO - 1);
    int y0c = min(max(y0, 0), HO - 1), y1c = min(max(y1, 0), HO - 1);

    Bilin r;
    r.w0 = i00 ? (1.f - wx) * (1.f - wy) : 0.f;
    r.w1 = i01 ? wx * (1.f - wy)         : 0.f;
    r.w2 = i10 ? (1.f - wx) * wy         : 0.f;
    r.w3 = i11 ? wx * wy                 : 0.f;
    const float* base = g_fmap + (size_t)b * HWO * COUT;
    r.p0 = base + (size_t)(y0c * WO + x0c) * COUT;
    r.p1 = base + (size_t)(y0c * WO + x1c) * COUT;
    r.p2 = base + (size_t)(y1c * WO + x0c) * COUT;
    r.p3 = base + (size_t)(y1c * WO + x1c) * COUT;
    return r;
}

// ---------------- kernel 6: LN + confidence + gumbel (warp per ada token) ---
__global__ void k_conf(const float* __restrict__ pos,
                       const float* __restrict__ ln_g, const float* __restrict__ ln_b,
                       const float* __restrict__ cw, const float* __restrict__ cb,
                       const float* __restrict__ noise) {
    int wid  = (blockIdx.x * blockDim.x + threadIdx.x) >> 5;
    int lane = threadIdx.x & 31;
    if (wid >= Bq * NA) return;
    int b = wid / NA;
    int j = wid % NA;
    int n = NG + j;

    float p0 = pos[((size_t)b * NTOK + n) * 2 + 0];
    float p1 = pos[((size_t)b * NTOK + n) * 2 + 1];
    Bilin bl = bilin_setup(b, p0, p1);

    float s1 = 0.f, s2 = 0.f, sxw = 0.f, sgw = 0.f, sbw = 0.f;
    for (int c = lane; c < COUT; c += 32) {
        float xc = bl.w0 * bl.p0[c] + bl.w1 * bl.p1[c]
                 + bl.w2 * bl.p2[c] + bl.w3 * bl.p3[c];
        float wc = cw[c];
        float gv = ln_g[c] * wc;
        s1 += xc;
        s2 += xc * xc;
        sxw += xc * gv;
        sgw += gv;
        sbw += ln_b[c] * wc;
    }
    #pragma unroll
    for (int o = 16; o > 0; o >>= 1) {
        s1  += __shfl_xor_sync(0xffffffffu, s1,  o);
        s2  += __shfl_xor_sync(0xffffffffu, s2,  o);
        sxw += __shfl_xor_sync(0xffffffffu, sxw, o);
        sgw += __shfl_xor_sync(0xffffffffu, sgw, o);
        sbw += __shfl_xor_sync(0xffffffffu, sbw, o);
    }
    if (lane == 0) {
        float mu  = s1 * (1.f / (float)COUT);
        float var = s2 * (1.f / (float)COUT) - mu * mu;
        float rs  = rsqrtf(var + 1e-5f);
        float conf = rs * (sxw - mu * sgw) + sbw + cb[0];
        float nz = noise[(size_t)b * NA + j];
        float g  = -logf(-logf(nz + 1e-6f) + 1e-6f);
        g_pert[wid] = conf + g;   // T = 1.0
    }
}

// ---------------- kernel 7: per-batch top-k via bitonic sort -----------------
__global__ void __launch_bounds__(1024) k_sort() {
    __shared__ unsigned long long s[SORTN];
    int b = blockIdx.x;
    int t = threadIdx.x;

    for (int i = t; i < SORTN; i += 1024) {
        unsigned long long key;
        if (i < NA) {
            float v = g_pert[b * NA + i];
            unsigned u = __float_as_uint(v);
            u = (u & 0x80000000u) ? ~u : (u | 0x80000000u);
            key = (((unsigned long long)(~u)) << 32) | (unsigned)i;
        } else {
            key = 0xFFFFFFFFFFFFFFFFull;
        }
        s[i] = key;
    }
    __syncthreads();

    for (int k = 2; k <= SORTN; k <<= 1) {
        for (int jj = k >> 1; jj > 0; jj >>= 1) {
            for (int i = t; i < SORTN; i += 1024) {
                int l = i ^ jj;
                if (l > i) {
                    unsigned long long a = s[i], c = s[l];
                    bool up = ((i & k) == 0);
                    if ((a > c) == up) { s[i] = c; s[l] = a; }
                }
            }
            __syncthreads();
        }
    }
    for (int i = t; i < SEL; i += 1024)
        g_idx[b * SEL + i] = (int)(unsigned)(s[i] & 0xFFFFFFFFull);
}

// ---------------- kernel 8: gather output (x_down then pos_down) -------------
__global__ void __launch_bounds__(320) k_gather(const float* __restrict__ pos,
                                                float* __restrict__ out) {
    int tok = blockIdx.x;
    int b = tok / NOUT, j = tok % NOUT;
    int n = (j < NG) ? j : (NG + g_idx[b * SEL + (j - NG)]);

    float p0 = pos[((size_t)b * NTOK + n) * 2 + 0];
    float p1 = pos[((size_t)b * NTOK + n) * 2 + 1];
    Bilin bl = bilin_setup(b, p0, p1);

    int c = threadIdx.x;
    float xc = bl.w0 * bl.p0[c] + bl.w1 * bl.p1[c]
             + bl.w2 * bl.p2[c] + bl.w3 * bl.p3[c];
    out[(size_t)tok * COUT + c] = xc;

    if (c < 2) {
        float* po = out + (size_t)Bq * NOUT * COUT + (size_t)tok * 2;
        po[c] = (c == 0) ? p0 : p1;
    }
}

// ---------------- launcher ---------------------------------------------------
extern "C" void kernel_launch(void* const* d_in, const int* in_sizes, int n_in,
                              void* d_out, int out_size) {
    const float* x      = (const float*)d_in[0];
    const float* pos    = (const float*)d_in[1];
    const float* conv_w = (const float*)d_in[2];
    const float* conv_b = (const float*)d_in[3];
    const float* ln_g   = (const float*)d_in[4];
    const float* ln_b   = (const float*)d_in[5];
    const float* conf_w = (const float*)d_in[6];
    const float* conf_b = (const float*)d_in[7];
    const float* noise  = (const float*)d_in[8];
    float* out = (float*)d_out;

    {   // zero scatter buffer
        const int n4 = (Bq * CP1 * HW) / 4;
        k_zero<<<(n4 + 255) / 256, 256>>>();
    }
    k_wtr<<<(COUT * KTOT + 255) / 256, 256>>>(conv_w);
    k_scatter<<<(Bq * NTOK + 1) / 2, 256>>>(x, pos);
    k_norm<<<(Bq * HW + 255) / 256, 256>>>();
    {   // horizontal blur: 4 rows per 256-thread block
        int rows = Bq * CP1 * Hh;
        k_blurh<<<rows / 4, 256>>>();
    }
    k_blurv<<<(Bq * HW + 255) / 256, 256>>>();

    dim3 cgrid(COUT / 64, HO / 4, Bq);   // (5, 7, 32)
    k_conv<<<cgrid, 224>>>(conv_b);

    k_conf<<<(Bq * NA * 32) / 256, 256>>>(pos, ln_g, ln_b, conf_w, conf_b, noise);
    k_sort<<<Bq, 1024>>>();
    k_gather<<<Bq * NOUT, 320>>>(pos, out);
}

// round 3
// speedup vs baseline: 1.8813x; 1.2504x over previous
#include <cuda_runtime.h>
#include <math.h>

// ---------------- problem constants (fixed shapes for this instance) --------
#define Bq    32
#define NTOK  3136
#define CIN   128
#define CP1   129
#define CPAD  132           // channel stride (float4 aligned, 528B)
#define Hh    56
#define Wq    56
#define HW    3136          // 56*56
#define HO    28
#define WO    28
#define HWO   784           // 28*28
#define COUT  320
#define NG    196
#define NA    2940          // NTOK - NG
#define SEL   588           // ceil(3136*0.25) - 196
#define NOUT  784           // NG + SEL
#define SORTN 4096
#define KTOT  1152          // 128*9

// ---------------- scratch (device globals; no allocations allowed) ----------
// g_feat / g_tmp are channel-innermost: [b][y][x][c], c-stride CPAD
__device__ float g_feat[Bq * HW * CPAD];
__device__ float g_tmp [Bq * HW * CPAD];
__device__ float g_fmap[Bq * HWO * COUT];    // conv output, NHWC layout
__device__ float g_wT  [KTOT * COUT];        // transposed conv weights [ci*9+k][co]
__device__ float g_pert[Bq * NA];            // perturbed confidences
__device__ int   g_idx [Bq * SEL];           // top-k indices (sorted order)

// ---------------- separable Gaussian (ksize=9, sigma=2), compile-time -------
__device__ __forceinline__ float gw9(int i) {
    const float e0 = 1.0f;
    const float e1 = 0.88249690258459546f;   // exp(-1/8)
    const float e2 = 0.60653065971263342f;   // exp(-4/8)
    const float e3 = 0.32465246735834974f;   // exp(-9/8)
    const float e4 = 0.13533528323661270f;   // exp(-16/8)
    const float S  = 1.0f + 2.0f*(e1 + e2 + e3 + e4);
    int d = i - 4; d = d < 0 ? -d : d;
    float e = (d == 0) ? e0 : (d == 1) ? e1 : (d == 2) ? e2 : (d == 3) ? e3 : e4;
    return e / S;
}

// ---------------- packed f32x2 helpers (SASS FFMA2) --------------------------
__device__ __forceinline__ unsigned long long pack2(float x) {
    unsigned long long r;
    asm("mov.b64 %0, {%1, %1};" : "=l"(r) : "f"(x));
    return r;
}
__device__ __forceinline__ void fma2(unsigned long long& d,
                                     unsigned long long a, unsigned long long b) {
    asm("fma.rn.f32x2 %0, %1, %2, %0;" : "+l"(d) : "l"(a), "l"(b));
}
__device__ __forceinline__ float2 unpack2(unsigned long long v) {
    float2 f;
    asm("mov.b64 {%0, %1}, %2;" : "=f"(f.x), "=f"(f.y) : "l"(v));
    return f;
}

// ---------------- kernel 0: zero the scatter buffer --------------------------
__global__ void k_zero() {
    int i = blockIdx.x * blockDim.x + threadIdx.x;
    float4* p = reinterpret_cast<float4*>(g_feat);
    const int n4 = (Bq * HW * CPAD) / 4;
    if (i < n4) p[i] = make_float4(0.f, 0.f, 0.f, 0.f);
}

// ---------------- kernel 0b: transpose conv weights to [ci*9+k][co] ---------
__global__ void k_wtr(const float* __restrict__ w) {
    int i = blockIdx.x * blockDim.x + threadIdx.x;     // over COUT*KTOT
    if (i >= COUT * KTOT) return;
    int co = i / KTOT;
    int r  = i % KTOT;                                  // r = ci*9 + ky*3 + kx
    g_wT[(size_t)r * COUT + co] = w[i];
}

// ---------------- kernel 1: token -> map scatter (coalesced atomics) --------
__global__ void k_scatter(const float* __restrict__ x, const float* __restrict__ pos) {
    int tok = blockIdx.x * 2 + (threadIdx.x >> 7);
    int c   = threadIdx.x & 127;
    if (tok >= Bq * NTOK) return;
    int b = tok / NTOK;

    float p0 = pos[(size_t)tok * 2 + 0];
    float p1 = pos[(size_t)tok * 2 + 1];
    p0 = fminf(fmaxf(p0, -1.f), 1.f);
    p1 = fminf(fmaxf(p1, -1.f), 1.f);
    int lx = (int)rintf(0.5f * (p0 + 1.0f) * (float)Wq - 0.5f);
    int ly = (int)rintf(0.5f * (p1 + 1.0f) * (float)Hh - 0.5f);
    lx = min(max(lx, 0), Wq - 1);
    ly = min(max(ly, 0), Hh - 1);
    int cell = ly * Wq + lx;

    float* base = g_feat + ((size_t)b * HW + cell) * CPAD;
    atomicAdd(base + c, x[(size_t)tok * CIN + c]);
    if (c == 0) atomicAdd(base + 128, 1.0f);
}

// ---------------- kernel 2: normalize by count, binarize mask (warp/cell) ---
__global__ void __launch_bounds__(256) k_norm() {
    int w = (blockIdx.x * blockDim.x + threadIdx.x) >> 5;
    int lane = threadIdx.x & 31;
    if (w >= Bq * HW) return;
    float* p = g_feat + (size_t)w * CPAD;
    float m = p[128];                       // warp-uniform broadcast load
    if (m <= 0.f) return;                   // empty cell: zeros + mask 0 already
    float inv = 1.f / (m + 1e-6f);
    float4* v4 = reinterpret_cast<float4*>(p);
    float4 v = v4[lane];
    v.x *= inv; v.y *= inv; v.z *= inv; v.w *= inv;
    v4[lane] = v;
    if (lane == 0) p[128] = 1.f;
}

// ---------------- kernel 3: horizontal 9-tap blur (block per (b,y) row) -----
__global__ void __launch_bounds__(256) k_blurh() {
    __shared__ float4 s[64 * 33];           // x in [-4,60), 33 float4 per x
    int row = blockIdx.x;                    // over Bq*Hh
    const float4* in4 = reinterpret_cast<const float4*>(g_feat + (size_t)row * Wq * CPAD);
    float4*       out4 = reinterpret_cast<float4*>(g_tmp + (size_t)row * Wq * CPAD);
    int t = threadIdx.x;

    for (int i = t; i < 64 * 33; i += 256) {
        int c4 = i % 33;
        int xs = i / 33;
        int xm = xs - 4;
        float4 v = make_float4(0.f, 0.f, 0.f, 0.f);
        if ((unsigned)xm < (unsigned)Wq) v = in4[xm * 33 + c4];
        s[xs * 33 + c4] = v;
    }
    __syncthreads();

    for (int i = t; i < Wq * 33; i += 256) {
        int c4 = i % 33;
        int x  = i / 33;
        float4 acc = make_float4(0.f, 0.f, 0.f, 0.f);
        #pragma unroll
        for (int k = 0; k < 9; k++) {
            float wk = gw9(k);
            float4 v = s[(x + k) * 33 + c4];
            acc.x += wk * v.x; acc.y += wk * v.y;
            acc.z += wk * v.z; acc.w += wk * v.w;
        }
        out4[i] = acc;
    }
}

// ---------------- kernel 4: vertical blur + hole-fill (block per (b,y)) -----
__global__ void __launch_bounds__(256) k_blurv() {
    __shared__ float s_scale[Wq];
    int blk = blockIdx.x;                    // over Bq*Hh
    int b = blk / Hh, y = blk % Hh;
    int t = threadIdx.x;

    // per-block vertical tap weights / row bases (uniform)
    float wv[9];
    const float* tb[9];
    #pragma unroll
    for (int k = 0; k < 9; k++) {
        int yy = y + k - 4;
        bool ok = (yy >= 0 && yy < Hh);
        wv[k] = ok ? gw9(k) : 0.f;
        int yc = ok ? yy : 0;
        tb[k] = g_tmp + ((size_t)b * HW + yc * Wq) * CPAD;
    }
    const float* fbase = g_feat + ((size_t)b * HW + y * Wq) * CPAD;

    if (t < Wq) {
        float m = fbase[t * CPAD + 128];
        float scale = 0.f;
        if (m <= 0.f) {                      // hole: compute mask-blur scale
            float fm = 0.f;
            #pragma unroll
            for (int k = 0; k < 9; k++) fm += wv[k] * tb[k][t * CPAD + 128];
            scale = (fm > 0.f) ? (1.f / fmaxf(fm, 1e-6f)) : 0.f;
        }
        s_scale[t] = scale;
    }
    __syncthreads();

    for (int i = t; i < Wq * 32; i += 256) {
        int c4 = i % 32;                     // channels 0..127 only
        int x  = i / 32;
        float sc = s_scale[x];
        if (sc == 0.f) continue;
        float4 fi = make_float4(0.f, 0.f, 0.f, 0.f);
        #pragma unroll
        for (int k = 0; k < 9; k++) {
            float wk = wv[k];
            const float4* p = reinterpret_cast<const float4*>(tb[k] + x * CPAD);
            float4 v = p[c4];
            fi.x += wk * v.x; fi.y += wk * v.y;
            fi.z += wk * v.z; fi.w += wk * v.w;
        }
        float4* fp = reinterpret_cast<float4*>(const_cast<float*>(fbase) + x * CPAD);
        float4 f = fp[c4];
        f.x += fi.x * sc; f.y += fi.y * sc;
        f.z += fi.z * sc; f.w += fi.w * sc;
        fp[c4] = f;
    }
}

// ---------------- kernel 5: 3x3 stride-2 conv 128->320 via packed FFMA2 -----
#define CI_CHUNK 8
__global__ void __launch_bounds__(224) k_conv(const float* __restrict__ bias) {
    __shared__ float2 s_pack[CI_CHUNK][6][60];   // [ci][rp*3+ky][xx]
    __shared__ float  s_w  [CI_CHUNK][9][64];    // [ci][k][co_local]

    int b   = blockIdx.z;
    int oy0 = blockIdx.y * 4;
    int co0 = blockIdx.x * 64;
    int t   = threadIdx.x;
    int co_g = t & 15;          // 4 co each
    int px_g = (t >> 4) % 7;    // 4 px each
    int rp   = t / 112;         // 0..1 (row pair)

    unsigned long long acc[16];
    #pragma unroll
    for (int i = 0; i < 16; i++) acc[i] = 0ull;

    const float* inb = g_feat + (size_t)b * HW * CPAD;

    for (int cc = 0; cc < 128; cc += CI_CHUNK) {
        __syncthreads();
        // fill packed input tile: ci fastest -> coalesced 32B global reads
        for (int i = t; i < CI_CHUNK * 6 * 57; i += 224) {
            int ci = i & 7;
            int xx = (i >> 3) % 57;
            int pk = i / (8 * 57);
            int rp_f = pk / 3, ky = pk % 3;
            int iy_a = 2 * (oy0 + 2 * rp_f) - 1 + ky;
            int iy_b = iy_a + 2;
            int ix = xx - 1;
            const float* p = inb + (cc + ci);
            float va = 0.f, vb = 0.f;
            if ((unsigned)ix < (unsigned)Wq) {
                if ((unsigned)iy_a < (unsigned)Hh) va = p[(size_t)(iy_a * Wq + ix) * CPAD];
                if ((unsigned)iy_b < (unsigned)Hh) vb = p[(size_t)(iy_b * Wq + ix) * CPAD];
            }
            s_pack[ci][pk][xx] = make_float2(va, vb);
        }
        // fill weights: coalesced from g_wT
        for (int i = t; i < CI_CHUNK * 9 * 64; i += 224) {
            int co = i & 63;
            int k  = (i >> 6) % 9;
            int ci = i / (64 * 9);
            s_w[ci][k][co] = g_wT[((size_t)(cc + ci) * 9 + k) * COUT + co0 + co];
        }
        __syncthreads();

        for (int ci = 0; ci < CI_CHUNK; ci++) {
            #pragma unroll
            for (int ky = 0; ky < 3; ky++) {
                const float2* prow = &s_pack[ci][rp * 3 + ky][8 * px_g];
                #pragma unroll
                for (int kx = 0; kx < 3; kx++) {
                    const int k = ky * 3 + kx;
                    float4 w4 = *reinterpret_cast<const float4*>(&s_w[ci][k][co_g * 4]);
                    unsigned long long wp0 = pack2(w4.x);
                    unsigned long long wp1 = pack2(w4.y);
                    unsigned long long wp2 = pack2(w4.z);
                    unsigned long long wp3 = pack2(w4.w);
                    #pragma unroll
                    for (int sub = 0; sub < 4; sub++) {
                        unsigned long long a =
                            *reinterpret_cast<const unsigned long long*>(&prow[2 * sub + kx]);
                        fma2(acc[0 * 4 + sub], a, wp0);
                        fma2(acc[1 * 4 + sub], a, wp1);
                        fma2(acc[2 * 4 + sub], a, wp2);
                        fma2(acc[3 * 4 + sub], a, wp3);
                    }
                }
            }
        }
    }

    int y0 = oy0 + 2 * rp;
    size_t base0 = ((size_t)b * HWO + y0 * WO) * COUT;
    #pragma unroll
    for (int o = 0; o < 4; o++) {
        int co = co0 + co_g * 4 + o;
        float bs = bias[co];
        #pragma unroll
        for (int sub = 0; sub < 4; sub++) {
            int px = px_g * 4 + sub;
            float2 f = unpack2(acc[o * 4 + sub]);
            g_fmap[base0 + (size_t)px * COUT + co]        = f.x + bs;
            g_fmap[base0 + (size_t)(WO + px) * COUT + co] = f.y + bs;
        }
    }
}

// ---------------- bilinear helper (fmap is NHWC, 28x28x320) -----------------
struct Bilin { float w0, w1, w2, w3; const float *p0, *p1, *p2, *p3; };

__device__ __forceinline__ Bilin bilin_setup(int b, float px, float py) {
    float gx = ((px + 1.f) * (float)WO - 1.f) * 0.5f;
    float gy = ((py + 1.f) * (float)HO - 1.f) * 0.5f;
    float x0f = floorf(gx), y0f = floorf(gy);
    float wx = gx - x0f, wy = gy - y0f;
    int x0 = (int)x0f, y0 = (int)y0f;
    int x1 = x0 + 1,   y1 = y0 + 1;

    bool i00 = (x0 >= 0 && x0 < WO && y0 >= 0 && y0 < HO);
    bool i01 = (x1 >= 0 && x1 < WO && y0 >= 0 && y0 < HO);
    bool i10 = (x0 >= 0 && x0 < WO && y1 >= 0 && y1 < HO);
    bool i11 = (x1 >= 0 && x1 < WO && y1 >= 0 && y1 < HO);
    int x0c = min(max(x0, 0), WO - 1), x1c = min(max(x1, 0), WO - 1);
    int y0c = min(max(y0, 0), HO - 1), y1c = min(max(y1, 0), HO - 1);

    Bilin r;
    r.w0 = i00 ? (1.f - wx) * (1.f - wy) : 0.f;
    r.w1 = i01 ? wx * (1.f - wy)         : 0.f;
    r.w2 = i10 ? (1.f - wx) * wy         : 0.f;
    r.w3 = i11 ? wx * wy                 : 0.f;
    const float* base = g_fmap + (size_t)b * HWO * COUT;
    r.p0 = base + (size_t)(y0c * WO + x0c) * COUT;
    r.p1 = base + (size_t)(y0c * WO + x1c) * COUT;
    r.p2 = base + (size_t)(y1c * WO + x0c) * COUT;
    r.p3 = base + (size_t)(y1c * WO + x1c) * COUT;
    return r;
}

// ---------------- kernel 6: LN + confidence + gumbel (warp per ada token) ---
__global__ void k_conf(const float* __restrict__ pos,
                       const float* __restrict__ ln_g, const float* __restrict__ ln_b,
                       const float* __restrict__ cw, const float* __restrict__ cb,
                       const float* __restrict__ noise) {
    int wid  = (blockIdx.x * blockDim.x + threadIdx.x) >> 5;
    int lane = threadIdx.x & 31;
    if (wid >= Bq * NA) return;
    int b = wid / NA;
    int j = wid % NA;
    int n = NG + j;

    float p0 = pos[((size_t)b * NTOK + n) * 2 + 0];
    float p1 = pos[((size_t)b * NTOK + n) * 2 + 1];
    Bilin bl = bilin_setup(b, p0, p1);

    float s1 = 0.f, s2 = 0.f, sxw = 0.f, sgw = 0.f, sbw = 0.f;
    for (int c = lane; c < COUT; c += 32) {
        float xc = bl.w0 * bl.p0[c] + bl.w1 * bl.p1[c]
                 + bl.w2 * bl.p2[c] + bl.w3 * bl.p3[c];
        float wc = cw[c];
        float gv = ln_g[c] * wc;
        s1 += xc;
        s2 += xc * xc;
        sxw += xc * gv;
        sgw += gv;
        sbw += ln_b[c] * wc;
    }
    #pragma unroll
    for (int o = 16; o > 0; o >>= 1) {
        s1  += __shfl_xor_sync(0xffffffffu, s1,  o);
        s2  += __shfl_xor_sync(0xffffffffu, s2,  o);
        sxw += __shfl_xor_sync(0xffffffffu, sxw, o);
        sgw += __shfl_xor_sync(0xffffffffu, sgw, o);
        sbw += __shfl_xor_sync(0xffffffffu, sbw, o);
    }
    if (lane == 0) {
        float mu  = s1 * (1.f / (float)COUT);
        float var = s2 * (1.f / (float)COUT) - mu * mu;
        float rs  = rsqrtf(var + 1e-5f);
        float conf = rs * (sxw - mu * sgw) + sbw + cb[0];
        float nz = noise[(size_t)b * NA + j];
        float g  = -logf(-logf(nz + 1e-6f) + 1e-6f);
        g_pert[wid] = conf + g;   // T = 1.0
    }
}

// ---------------- kernel 7: per-batch top-k via bitonic sort -----------------
__global__ void __launch_bounds__(1024) k_sort() {
    __shared__ unsigned long long s[SORTN];
    int b = blockIdx.x;
    int t = threadIdx.x;

    for (int i = t; i < SORTN; i += 1024) {
        unsigned long long key;
        if (i < NA) {
            float v = g_pert[b * NA + i];
            unsigned u = __float_as_uint(v);
            u = (u & 0x80000000u) ? ~u : (u | 0x80000000u);
            key = (((unsigned long long)(~u)) << 32) | (unsigned)i;
        } else {
            key = 0xFFFFFFFFFFFFFFFFull;
        }
        s[i] = key;
    }
    __syncthreads();

    for (int k = 2; k <= SORTN; k <<= 1) {
        for (int jj = k >> 1; jj > 0; jj >>= 1) {
            for (int i = t; i < SORTN; i += 1024) {
                int l = i ^ jj;
                if (l > i) {
                    unsigned long long a = s[i], c = s[l];
                    bool up = ((i & k) == 0);
                    if ((a > c) == up) { s[i] = c; s[l] = a; }
                }
            }
            __syncthreads();
        }
    }
    for (int i = t; i < SEL; i += 1024)
        g_idx[b * SEL + i] = (int)(unsigned)(s[i] & 0xFFFFFFFFull);
}

// ---------------- kernel 8: gather output (x_down then pos_down) -------------
__global__ void __launch_bounds__(320) k_gather(const float* __restrict__ pos,
                                                float* __restrict__ out) {
    int tok = blockIdx.x;
    int b = tok / NOUT, j = tok % NOUT;
    int n = (j < NG) ? j : (NG + g_idx[b * SEL + (j - NG)]);

    float p0 = pos[((size_t)b * NTOK + n) * 2 + 0];
    float p1 = pos[((size_t)b * NTOK + n) * 2 + 1];
    Bilin bl = bilin_setup(b, p0, p1);

    int c = threadIdx.x;
    float xc = bl.w0 * bl.p0[c] + bl.w1 * bl.p1[c]
             + bl.w2 * bl.p2[c] + bl.w3 * bl.p3[c];
    out[(size_t)tok * COUT + c] = xc;

    if (c < 2) {
        float* po = out + (size_t)Bq * NOUT * COUT + (size_t)tok * 2;
        po[c] = (c == 0) ? p0 : p1;
    }
}

// ---------------- launcher ---------------------------------------------------
extern "C" void kernel_launch(void* const* d_in, const int* in_sizes, int n_in,
                              void* d_out, int out_size) {
    const float* x      = (const float*)d_in[0];
    const float* pos    = (const float*)d_in[1];
    const float* conv_w = (const float*)d_in[2];
    const float* conv_b = (const float*)d_in[3];
    const float* ln_g   = (const float*)d_in[4];
    const float* ln_b   = (const float*)d_in[5];
    const float* conf_w = (const float*)d_in[6];
    const float* conf_b = (const float*)d_in[7];
    const float* noise  = (const float*)d_in[8];
    float* out = (float*)d_out;

    {   // zero scatter buffer
        const int n4 = (Bq * HW * CPAD) / 4;
        k_zero<<<(n4 + 255) / 256, 256>>>();
    }
    k_wtr<<<(COUT * KTOT + 255) / 256, 256>>>(conv_w);
    k_scatter<<<(Bq * NTOK + 1) / 2, 256>>>(x, pos);
    k_norm<<<(Bq * HW * 32 + 255) / 256, 256>>>();
    k_blurh<<<Bq * Hh, 256>>>();
    k_blurv<<<Bq * Hh, 256>>>();

    dim3 cgrid(COUT / 64, HO / 4, Bq);   // (5, 7, 32)
    k_conv<<<cgrid, 224>>>(conv_b);

    k_conf<<<(Bq * NA * 32) / 256, 256>>>(pos, ln_g, ln_b, conf_w, conf_b, noise);
    k_sort<<<Bq, 1024>>>();
    k_gather<<<Bq * NOUT, 320>>>(pos, out);
}